// round 2
// baseline (speedup 1.0000x reference)
#include <cuda_runtime.h>
#include <math.h>

// Problem constants (fixed by dataset: B=64, NCROPS=2, T=2048, nb=32)
#define TT 2048
#define NT 256
#define CH (TT / NT)   // 8 elements per thread
#define ALPHA_F 0.7f
#define MIN_MINING_STEP 50

__device__ float g_partial[64];

__global__ __launch_bounds__(NT, 1)
void glance_main(const float* __restrict__ scores,
                 const int* __restrict__ point_label,
                 const int* __restrict__ seqlen,
                 const int* __restrict__ step_p)
{
    const int b = blockIdx.x;     // video index 0..nb-1
    const int t = threadIdx.x;

    __shared__ float sprob[TT];
    __shared__ float stemp[TT];
    __shared__ unsigned char sanch[TT];
    __shared__ unsigned char sgrow[TT];
    __shared__ int   ibuf[NT];
    __shared__ float fbuf[NT];
    __shared__ int   s_any;

    if (t == 0) s_any = 0;

    const float* r0 = scores + (size_t)(2 * b) * TT;
    const float* r1 = scores + (size_t)(2 * b + 1) * TT;
    const int*   pl = point_label + (size_t)b * TT;

    // Phase 1: probs = mean over crops of sigmoid(scores); load anchors
    for (int j = t; j < TT; j += NT) {
        float a = r0[j], c = r1[j];
        float p = 0.5f * (1.0f / (1.0f + expf(-a)) + 1.0f / (1.0f + expf(-c)));
        sprob[j] = p;
        int af = (pl[j] > 0) ? 1 : 0;
        sanch[j] = (unsigned char)af;
        sgrow[j] = 0;
        if (af) s_any = 1;
    }
    __syncthreads();

    const int step = step_p[0];
    const int L = seqlen[b];
    const bool mining = (step >= MIN_MINING_STEP);

    // Phase 2: gaussian kernel mining == per-anchor outward walks.
    // Fwd growth masked by j < L (matches reference: g_fwd & (arange < seqlen)).
    if (mining) {
        for (int p = t; p < TT; p += NT) {
            if (sanch[p]) {
                const float thr = ALPHA_F * sprob[p];
                // forward walk
                for (int j = p + 1; j < TT; ++j) {
                    if (sprob[j] >= thr) {
                        if (j < L) sgrow[j] = 1;
                        if (sanch[j]) break;   // scan resets at next anchor
                    } else break;              // cumulative-AND fails
                }
                // backward walk
                for (int j = p - 1; j >= 0; --j) {
                    if (sprob[j] >= thr) {
                        sgrow[j] = 1;
                        if (sanch[j]) break;
                    } else break;
                }
            }
        }
    }
    __syncthreads();

    // Phase 3: splat. max over anchors p of Wn[p,i] reduces (to < fp32 ulp)
    // to exp(-(2*dist/(T-1))^2 / (2*sigma^2)) with dist = nearest mask elem.
    // Distance transform via chunked prev/next-set scans.
    const int base = t * CH;
    const int SENT_LO = INT_MIN / 2;
    const int SENT_HI = INT_MAX / 2;

    // prev-set inclusive max scan
    int last = SENT_LO;
    #pragma unroll
    for (int k = 0; k < CH; ++k) {
        int j = base + k;
        if (sanch[j] | sgrow[j]) last = j;
    }
    ibuf[t] = last;
    __syncthreads();
    #pragma unroll
    for (int off = 1; off < NT; off <<= 1) {
        int v = ibuf[t];
        if (t >= off) v = max(v, ibuf[t - off]);
        __syncthreads();
        ibuf[t] = v;
        __syncthreads();
    }
    const int carry_prev = (t > 0) ? ibuf[t - 1] : SENT_LO;
    __syncthreads();

    // next-set inclusive min (suffix) scan
    int first = SENT_HI;
    #pragma unroll
    for (int k = CH - 1; k >= 0; --k) {
        int j = base + k;
        if (sanch[j] | sgrow[j]) first = j;
    }
    ibuf[t] = first;
    __syncthreads();
    #pragma unroll
    for (int off = 1; off < NT; off <<= 1) {
        int v = ibuf[t];
        if (t + off < NT) v = min(v, ibuf[t + off]);
        __syncthreads();
        ibuf[t] = v;
        __syncthreads();
    }
    const int carry_next = (t < NT - 1) ? ibuf[t + 1] : SENT_HI;
    __syncthreads();

    // exp(-d^2/(2 sigma^2)) with d = 2*dist/(T-1), sigma=0.1 -> coeff = -200/(T-1)^2
    const float coef = -200.0f / ((float)(TT - 1) * (float)(TT - 1));

    int nxt[CH];
    {
        int run = carry_next;
        #pragma unroll
        for (int k = CH - 1; k >= 0; --k) {
            int j = base + k;
            if (sanch[j] | sgrow[j]) run = j;
            nxt[k] = run;
        }
    }
    float lmin = 1e30f, lmax = -1e30f;
    {
        int run = carry_prev;
        #pragma unroll
        for (int k = 0; k < CH; ++k) {
            int j = base + k;
            if (sanch[j] | sgrow[j]) run = j;
            int d1 = j - run;          // safe: j - INT_MIN/2 < INT_MAX
            int d2 = nxt[k] - j;
            float fd = (float)min(d1, d2);
            float g = expf(coef * fd * fd);   // 0 when no anchor on either side
            stemp[j] = g;
            lmin = fminf(lmin, g);
            lmax = fmaxf(lmax, g);
        }
    }

    // block min/max reductions
    fbuf[t] = lmin;
    __syncthreads();
    #pragma unroll
    for (int off = NT / 2; off > 0; off >>= 1) {
        if (t < off) fbuf[t] = fminf(fbuf[t], fbuf[t + off]);
        __syncthreads();
    }
    const float tmin = fbuf[0];
    __syncthreads();
    fbuf[t] = lmax;
    __syncthreads();
    #pragma unroll
    for (int off = NT / 2; off > 0; off >>= 1) {
        if (t < off) fbuf[t] = fmaxf(fbuf[t], fbuf[t + off]);
        __syncthreads();
    }
    const float tmax = fbuf[0];
    __syncthreads();

    // Phase 4: BCE partial sum
    const int any_a = s_any;
    const bool donorm = (tmax > tmin);
    const float invden = donorm ? (1.0f / (tmax - tmin)) : 0.0f;

    float lsum = 0.0f;
    for (int j = t; j < TT; j += NT) {
        float g = stemp[j];
        float r = donorm ? (g - tmin) * invden : g;
        if (!any_a) r = 0.0f;
        float s = sprob[j];
        lsum += -(r * logf(s) + (1.0f - r) * log1pf(-s));
    }
    fbuf[t] = lsum;
    __syncthreads();
    #pragma unroll
    for (int off = NT / 2; off > 0; off >>= 1) {
        if (t < off) fbuf[t] += fbuf[t + off];
        __syncthreads();
    }
    if (t == 0) g_partial[b] = fbuf[0];
}

__global__ void glance_reduce(float* __restrict__ out, int nb)
{
    if (threadIdx.x == 0 && blockIdx.x == 0) {
        float s = 0.0f;
        for (int i = 0; i < nb; ++i) s += g_partial[i];   // fixed order: deterministic
        out[0] = s / ((float)nb * (float)TT);
    }
}

extern "C" void kernel_launch(void* const* d_in, const int* in_sizes, int n_in,
                              void* d_out, int out_size)
{
    const float* scores      = (const float*)d_in[0];
    // d_in[1] = labels (unused by the reference computation)
    const int*   point_label = (const int*)d_in[2];
    const int*   seqlen      = (const int*)d_in[3];
    const int*   step_p      = (const int*)d_in[4];
    float* out = (float*)d_out;

    const int B  = in_sizes[1];        // 64 (labels length)
    const int nb = B / 2;              // 32 abnormal videos

    glance_main<<<nb, NT>>>(scores, point_label, seqlen, step_p);
    glance_reduce<<<1, 32>>>(out, nb);
}

// round 6
// speedup vs baseline: 4.0932x; 4.0932x over previous
#include <cuda_runtime.h>
#include <math.h>

// Fixed dataset shape: B=64, NCROPS=2, T=2048, nb=32
#define TT 2048
#define NT 256
#define CH 8            // elements per thread
#define NW 8            // warps per block
#define ALPHA_F 0.7f
#define MIN_MINING_STEP 50
#define SENT_LO (-(1 << 30))

__device__ float g_partial[64];
__device__ int   g_count = 0;

// ---- block-wide exclusive max carry (thread aggregates -> exclusive prefix) ----
__device__ __forceinline__ int blk_excl_max(int agg, int* warr, int t, int ident)
{
    const int lane = t & 31, warp = t >> 5;
    int inc = agg;
    #pragma unroll
    for (int d = 1; d < 32; d <<= 1) {
        int v = __shfl_up_sync(0xffffffffu, inc, d);
        if (lane >= d) inc = max(inc, v);
    }
    if (lane == 31) warr[warp] = inc;
    __syncthreads();
    int wc = ident;
    #pragma unroll
    for (int w = 0; w < NW; ++w) {
        int vv = warr[w];
        if (w < warp) wc = max(wc, vv);
    }
    int le = __shfl_up_sync(0xffffffffu, inc, 1);
    if (lane == 0) le = ident;
    int carry = max(wc, le);
    __syncthreads();          // protect warr for next use
    return carry;
}

// ---- segmented-AND monoid: bit0 = value, bit1 = reset ----
__device__ __forceinline__ int segop(int a, int b)
{
    int v = (b & 2) ? (b & 1) : (a & b & 1);
    return v | ((a | b) & 2);
}

__device__ __forceinline__ int blk_excl_seg(int agg, int* warr, int t)
{
    const int lane = t & 31, warp = t >> 5;
    const int IDENT = 1;      // value=1 (true), reset=0
    int inc = agg;
    #pragma unroll
    for (int d = 1; d < 32; d <<= 1) {
        int v = __shfl_up_sync(0xffffffffu, inc, d);
        if (lane >= d) inc = segop(v, inc);
    }
    if (lane == 31) warr[warp] = inc;
    __syncthreads();
    int wc = IDENT;
    #pragma unroll
    for (int w = 0; w < NW; ++w) {
        int vv = warr[w];
        if (w < warp) wc = segop(wc, vv);
    }
    int le = __shfl_up_sync(0xffffffffu, inc, 1);
    if (lane == 0) le = IDENT;
    int carry = segop(wc, le);
    __syncthreads();
    return carry;
}

__global__ __launch_bounds__(NT, 1)
void glance_fused(const float* __restrict__ scores,
                  const int* __restrict__ point_label,
                  const int* __restrict__ seqlen,
                  const int* __restrict__ step_p,
                  float* __restrict__ out)
{
    const int b = blockIdx.x;
    const int t = threadIdx.x;

    __shared__ float sprob[TT];
    __shared__ int   snextd[TT];
    __shared__ unsigned char sanch[TT];
    __shared__ unsigned char smined[TT];
    __shared__ int   warr[NW];
    __shared__ float fmn[NW], fmx[NW], fsm[NW];

    const float* r0 = scores + (size_t)(2 * b) * TT;
    const float* r1 = scores + (size_t)(2 * b + 1) * TT;
    const int*   pl = point_label + (size_t)b * TT;

    // Phase 1: probs = mean-over-crops sigmoid; anchors
    int localAny = 0;
    for (int j = t; j < TT; j += NT) {
        float p = 0.5f * (1.0f / (1.0f + __expf(-r0[j])) +
                          1.0f / (1.0f + __expf(-r1[j])));
        sprob[j] = p;
        int af = (pl[j] > 0) ? 1 : 0;
        sanch[j]  = (unsigned char)af;
        smined[j] = (unsigned char)af;
        localAny |= af;
    }
    const int anyA = __syncthreads_or(localAny);   // barrier + any-anchor

    const int  L      = seqlen[b];
    const bool mining = (step_p[0] >= MIN_MINING_STEP);
    const int  base   = t * CH;

    // Phase 2: mining as parallel segmented scans (no serial walks).
    if (mining) {
        // ---- forward direction ----
        {
            int excl[CH]; int run = -1;
            #pragma unroll
            for (int k = 0; k < CH; ++k) {
                int pos = base + k; excl[k] = run;
                if (sanch[pos]) run = pos;
            }
            const int carry = blk_excl_max(run, warr, t, -1);  // PA exclusive
            int inc[CH], pa[CH]; int a = 1;
            #pragma unroll
            for (int k = 0; k < CH; ++k) {
                int pos = base + k;
                int PA = max(carry, excl[k]); pa[k] = PA;
                int r = (pos > 0 && sanch[pos - 1]) ? 2 : 0;
                int v = 1;
                if (PA >= 0) v = (sprob[pos] >= ALPHA_F * sprob[PA]) ? 1 : 0;
                a = segop(a, v | r); inc[k] = a;
            }
            const int c2 = blk_excl_seg(a, warr, t);
            #pragma unroll
            for (int k = 0; k < CH; ++k) {
                int pos = base + k;
                int g = segop(c2, inc[k]) & 1;
                if (g && pa[k] >= 0 && pos < L) smined[pos] = 1;
            }
        }
        // ---- backward direction (virtual u -> pos = TT-1-u) ----
        {
            int excl[CH]; int run = -1;
            #pragma unroll
            for (int k = 0; k < CH; ++k) {
                int u = base + k, pos = TT - 1 - u; excl[k] = run;
                if (sanch[pos]) run = u;
            }
            const int carry = blk_excl_max(run, warr, t, -1);
            int inc[CH], pa[CH]; int a = 1;
            #pragma unroll
            for (int k = 0; k < CH; ++k) {
                int u = base + k, pos = TT - 1 - u;
                int PA = max(carry, excl[k]); pa[k] = PA;
                int r = (u > 0 && sanch[pos + 1]) ? 2 : 0;
                int v = 1;
                if (PA >= 0) v = (sprob[pos] >= ALPHA_F * sprob[TT - 1 - PA]) ? 1 : 0;
                a = segop(a, v | r); inc[k] = a;
            }
            const int c2 = blk_excl_seg(a, warr, t);
            #pragma unroll
            for (int k = 0; k < CH; ++k) {
                int u = base + k, pos = TT - 1 - u;
                int g = segop(c2, inc[k]) & 1;
                if (g && pa[k] >= 0) smined[pos] = 1;
            }
        }
    }
    __syncthreads();

    // Phase 3a: next-set distance (bwd layout inclusive max over virtual idx)
    {
        int incl[CH]; int run = SENT_LO;
        #pragma unroll
        for (int k = 0; k < CH; ++k) {
            int u = base + k, pos = TT - 1 - u;
            if (smined[pos]) run = u;
            incl[k] = run;
        }
        const int carry = blk_excl_max(run, warr, t, SENT_LO);
        #pragma unroll
        for (int k = 0; k < CH; ++k) {
            int u = base + k, pos = TT - 1 - u;
            int uv = max(carry, incl[k]);
            snextd[pos] = u - uv;      // distance to next mined (or huge)
        }
    }
    __syncthreads();

    // Phase 3b: prev-set distance (fwd layout) + gaussian splat value.
    // max over anchors of Wn[p,i] == exp(-(2*d/(T-1))^2/(2*sigma^2)),
    // d = distance to nearest mined element (min-subtraction < fp32 ulp).
    float garr[CH];
    float lmin = 1e30f, lmax = -1e30f;
    {
        int incl[CH]; int run = SENT_LO;
        #pragma unroll
        for (int k = 0; k < CH; ++k) {
            int pos = base + k;
            if (smined[pos]) run = pos;
            incl[k] = run;
        }
        const int carry = blk_excl_max(run, warr, t, SENT_LO);
        const float coef = -200.0f / ((float)(TT - 1) * (float)(TT - 1));
        #pragma unroll
        for (int k = 0; k < CH; ++k) {
            int pos = base + k;
            int pv = max(carry, incl[k]);
            int d  = min(pos - pv, snextd[pos]);
            float fd = (float)d;
            float g = __expf(coef * fd * fd);   // ->0 when no mined elements
            garr[k] = g;
            lmin = fminf(lmin, g);
            lmax = fmaxf(lmax, g);
        }
    }

    // block min/max (warp butterfly + 8-entry smem)
    const int lane = t & 31, warp = t >> 5;
    float wmn = lmin, wmx = lmax;
    #pragma unroll
    for (int d = 16; d; d >>= 1) {
        wmn = fminf(wmn, __shfl_xor_sync(0xffffffffu, wmn, d));
        wmx = fmaxf(wmx, __shfl_xor_sync(0xffffffffu, wmx, d));
    }
    if (lane == 0) { fmn[warp] = wmn; fmx[warp] = wmx; }
    __syncthreads();
    float tmin = 1e30f, tmax = -1e30f;
    #pragma unroll
    for (int w = 0; w < NW; ++w) {
        tmin = fminf(tmin, fmn[w]);
        tmax = fmaxf(tmax, fmx[w]);
    }

    // Phase 4: min-max norm + BCE partial sum
    const bool donorm = (tmax > tmin);
    const float inv = donorm ? 1.0f / (tmax - tmin) : 0.0f;
    float lsum = 0.0f;
    #pragma unroll
    for (int k = 0; k < CH; ++k) {
        int pos = base + k;
        float g  = garr[k];
        float rr = donorm ? (g - tmin) * inv : g;
        if (!anyA) rr = 0.0f;
        float s = sprob[pos];
        lsum += -(rr * __logf(s) + (1.0f - rr) * __logf(1.0f - s));
    }
    #pragma unroll
    for (int d = 16; d; d >>= 1)
        lsum += __shfl_xor_sync(0xffffffffu, lsum, d);
    if (lane == 0) fsm[warp] = lsum;
    __syncthreads();

    if (t == 0) {
        float tot = 0.0f;
        #pragma unroll
        for (int w = 0; w < NW; ++w) tot += fsm[w];
        g_partial[b] = tot;
        __threadfence();
        int old = atomicAdd(&g_count, 1);
        if (old == (int)gridDim.x - 1) {
            // last block: deterministic fixed-order final reduce
            float s = 0.0f;
            const int nb = (int)gridDim.x;
            for (int i = 0; i < nb; ++i) s += g_partial[i];
            out[0] = s / ((float)nb * (float)TT);
            g_count = 0;              // reset for next graph replay
        }
    }
}

extern "C" void kernel_launch(void* const* d_in, const int* in_sizes, int n_in,
                              void* d_out, int out_size)
{
    const float* scores      = (const float*)d_in[0];
    // d_in[1] = labels (unused by the loss)
    const int*   point_label = (const int*)d_in[2];
    const int*   seqlen      = (const int*)d_in[3];
    const int*   step_p      = (const int*)d_in[4];
    float* out = (float*)d_out;

    const int B  = in_sizes[1];   // 64
    const int nb = B / 2;         // 32 abnormal videos

    glance_fused<<<nb, NT>>>(scores, point_label, seqlen, step_p, out);
}

// round 7
// speedup vs baseline: 5.6163x; 1.3721x over previous
#include <cuda_runtime.h>
#include <math.h>

// Fixed dataset shape: B=64, NCROPS=2, T=2048, nb=32
#define TT   2048
#define NT   512        // 16 warps: group0 = warps 0-7 (fwd), group1 = warps 8-15 (bwd)
#define GT   256        // threads per group
#define GCH  8          // elements per thread in group phases
#define CH4  4          // elements per thread in full-block phases
#define ALPHA_F 0.7f
#define MIN_MINING_STEP 50
#define SENT_LO (-(1 << 30))
#define BIGF 3.0e38f

__device__ float g_partial[64];
__device__ int   g_count = 0;

// group barrier (named): only the 256 threads of one group participate
__device__ __forceinline__ void gbar(int id) {
    asm volatile("bar.sync %0, %1;" :: "r"(id), "r"(GT) : "memory");
}

// ---- mining monoid: function (okIn,anchIn,hasIn) -> (okOut,anchOut,hasOut) ----
// fl bit0 = hasAnchor, bit1 = okPost (ok after last internal anchor)
struct MF { int fl; float aOut; float mPre; };

__device__ __forceinline__ MF mcomp(const MF L, const MF R) {
    MF C;
    const int lh = L.fl & 1, rh = R.fl & 1;
    C.aOut = rh ? R.aOut : L.aOut;
    C.mPre = lh ? L.mPre : fminf(L.mPre, R.mPre);
    int kp = rh ? (R.fl >> 1)
                : ((L.fl >> 1) & ((R.mPre >= ALPHA_F * L.aOut) ? 1 : 0));
    C.fl = (lh | rh) | ((kp & 1) << 1);
    return C;
}

// One mining direction: exact replay of the jax scan recurrence via
// serial-chunk + warp-shuffle scan + cross-warp compose (group-local).
__device__ __forceinline__ void mine_dir(
    const float* __restrict__ sprob, const unsigned char* __restrict__ sanch,
    unsigned char* __restrict__ smined,
    int* sfl, float* sa, float* sm,
    int gt, int lane, int wig, int wg, int barId, int rev, int L)
{
    const int base = gt * GCH;

    // pass 1: serial thread aggregate (compose 8 element functions)
    MF acc;
    #pragma unroll
    for (int k = 0; k < GCH; ++k) {
        int idx = base + k;
        int pos = rev ? (TT - 1 - idx) : idx;
        float s = sprob[pos];
        int   a = sanch[pos];
        MF e; e.fl = a ? 3 : 2; e.aOut = a ? s : 0.0f; e.mPre = a ? BIGF : s;
        acc = (k == 0) ? e : mcomp(acc, e);
    }

    // warp inclusive scan
    MF inc = acc;
    #pragma unroll
    for (int d = 1; d < 32; d <<= 1) {
        MF v;
        v.fl   = __shfl_up_sync(0xffffffffu, inc.fl,   d);
        v.aOut = __shfl_up_sync(0xffffffffu, inc.aOut, d);
        v.mPre = __shfl_up_sync(0xffffffffu, inc.mPre, d);
        if (lane >= d) inc = mcomp(v, inc);
    }
    if (lane == 31) { sfl[wg] = inc.fl; sa[wg] = inc.aOut; sm[wg] = inc.mPre; }
    gbar(barId);

    // prefix over preceding warps of this group (serial, 0-7 composes)
    MF wp; int hasWp = 0;
    const int wbase = wg - wig;
    for (int w = wbase; w < wg; ++w) {
        MF v; v.fl = sfl[w]; v.aOut = sa[w]; v.mPre = sm[w];
        wp = hasWp ? mcomp(wp, v) : v;
        hasWp = 1;
    }
    // thread-exclusive within warp
    MF te;
    te.fl   = __shfl_up_sync(0xffffffffu, inc.fl,   1);
    te.aOut = __shfl_up_sync(0xffffffffu, inc.aOut, 1);
    te.mPre = __shfl_up_sync(0xffffffffu, inc.mPre, 1);
    const int hasTe = (lane > 0);
    MF P; int hasP = 0;
    if (hasWp && hasTe)      { P = mcomp(wp, te); hasP = 1; }
    else if (hasWp)          { P = wp;            hasP = 1; }
    else if (hasTe)          { P = te;            hasP = 1; }

    // apply prefix to canonical init (ok=true, anch=0, has=false)
    int   has  = hasP ? (P.fl & 1) : 0;
    int   ok   = has ? ((P.fl >> 1) & 1) : 1;   // don't-care when has==0
    float anch = has ? P.aOut : 0.0f;

    // pass 2: serial replay emitting grown flags
    #pragma unroll
    for (int k = 0; k < GCH; ++k) {
        int idx = base + k;
        int pos = rev ? (TT - 1 - idx) : idx;
        float s = sprob[pos];
        int   a = sanch[pos];
        int cond  = (s >= ALPHA_F * anch) ? 1 : 0;
        int grown = ok & cond & has;
        if (grown && (rev || pos < L)) smined[pos] = 1;  // fwd masked by seqlen
        ok   = a ? 1 : grown;
        anch = a ? s : anch;
        has |= a;
    }
}

// Distance-to-previous-set (in idx coordinates) via group-local max scan
__device__ __forceinline__ void dist_dir(
    const unsigned char* __restrict__ smined, int* __restrict__ dout,
    int* iw, int gt, int lane, int wig, int wg, int barId, int rev)
{
    const int base = gt * GCH;
    int incl[GCH]; int run = SENT_LO;
    #pragma unroll
    for (int k = 0; k < GCH; ++k) {
        int idx = base + k;
        int pos = rev ? (TT - 1 - idx) : idx;
        if (smined[pos]) run = idx;
        incl[k] = run;
    }
    int v = run;
    #pragma unroll
    for (int d = 1; d < 32; d <<= 1) {
        int u = __shfl_up_sync(0xffffffffu, v, d);
        if (lane >= d) v = max(v, u);
    }
    if (lane == 31) iw[wg] = v;
    gbar(barId);
    int carry = SENT_LO;
    const int wbase = wg - wig;
    for (int w = wbase; w < wg; ++w) carry = max(carry, iw[w]);
    int te = __shfl_up_sync(0xffffffffu, v, 1);
    if (lane == 0) te = SENT_LO;
    carry = max(carry, te);
    #pragma unroll
    for (int k = 0; k < GCH; ++k) {
        int idx = base + k;
        int pos = rev ? (TT - 1 - idx) : idx;
        int pv = max(carry, incl[k]);
        dout[pos] = idx - pv;          // distance (huge when none)
    }
}

__global__ __launch_bounds__(NT, 1)
void glance_fused(const float* __restrict__ scores,
                  const int* __restrict__ point_label,
                  const int* __restrict__ seqlen,
                  const int* __restrict__ step_p,
                  float* __restrict__ out)
{
    const int b = blockIdx.x;
    const int t = threadIdx.x;

    __shared__ float sprob[TT];
    __shared__ int   sprevd[TT];
    __shared__ int   snextd[TT];
    __shared__ unsigned char sanch[TT];
    __shared__ unsigned char smined[TT];
    __shared__ int   sfl[16]; __shared__ float sa[16]; __shared__ float sm[16];
    __shared__ int   iw[16];
    __shared__ float fmn[16], fmx[16], fsm[16];

    // early scalar loads (overlap with phase 1 DRAM latency)
    const int L   = seqlen[b];
    const int stp = step_p[0];

    // Phase 1: vectorized sigmoid + crop-mean; probs kept in registers too
    const float4* r0 = (const float4*)(scores + (size_t)(2 * b) * TT);
    const float4* r1 = (const float4*)(scores + (size_t)(2 * b + 1) * TT);
    const int4*   pl = (const int4*)(point_label + (size_t)b * TT);
    const float4 av = r0[t];
    const float4 cv = r1[t];
    const int4   qv = pl[t];
    const float aa[4] = {av.x, av.y, av.z, av.w};
    const float cc[4] = {cv.x, cv.y, cv.z, cv.w};
    const int   qq[4] = {qv.x, qv.y, qv.z, qv.w};
    const int base4 = t * CH4;
    float pr[CH4];
    int localAny = 0;
    #pragma unroll
    for (int k = 0; k < CH4; ++k) {
        float p = 0.5f * (1.0f / (1.0f + __expf(-aa[k])) +
                          1.0f / (1.0f + __expf(-cc[k])));
        pr[k] = p;
        sprob[base4 + k] = p;
        int af = (qq[k] > 0) ? 1 : 0;
        sanch[base4 + k]  = (unsigned char)af;
        smined[base4 + k] = (unsigned char)af;
        localAny |= af;
    }
    const int anyA = __syncthreads_or(localAny);

    const int lane = t & 31, wg = t >> 5, grp = t >> 8, wig = wg & 7;
    const int gt = t & (GT - 1), barId = 1 + grp;

    // Phase 2: mining — fwd (group 0) and bwd (group 1) run CONCURRENTLY
    if (stp >= MIN_MINING_STEP) {
        mine_dir(sprob, sanch, smined, sfl, sa, sm,
                 gt, lane, wig, wg, barId, grp, L);
    }
    __syncthreads();

    // Phase 3: distance transforms — prev (group 0) / next (group 1) concurrent
    if (grp == 0) dist_dir(smined, sprevd, iw, gt, lane, wig, wg, barId, 0);
    else          dist_dir(smined, snextd, iw, gt, lane, wig, wg, barId, 1);
    __syncthreads();

    // Phase 4: gaussian splat from nearest-mined distance + block min/max.
    // max over anchors of Wn[p,i] == exp(-(2d/(T-1))^2/(2*sigma^2)), d = nearest.
    const float coef = -200.0f / ((float)(TT - 1) * (float)(TT - 1));
    float garr[CH4];
    float lmin = 1e30f, lmax = -1e30f;
    #pragma unroll
    for (int k = 0; k < CH4; ++k) {
        int pos = base4 + k;
        int d = min(sprevd[pos], snextd[pos]);
        float fd = (float)d;
        float g = __expf(coef * fd * fd);      // ->0 when no mined elements
        garr[k] = g;
        lmin = fminf(lmin, g);
        lmax = fmaxf(lmax, g);
    }
    #pragma unroll
    for (int d = 16; d; d >>= 1) {
        lmin = fminf(lmin, __shfl_xor_sync(0xffffffffu, lmin, d));
        lmax = fmaxf(lmax, __shfl_xor_sync(0xffffffffu, lmax, d));
    }
    if (lane == 0) { fmn[wg] = lmin; fmx[wg] = lmax; }
    __syncthreads();
    float tmin = 1e30f, tmax = -1e30f;
    #pragma unroll
    for (int w = 0; w < 16; ++w) {
        tmin = fminf(tmin, fmn[w]);
        tmax = fmaxf(tmax, fmx[w]);
    }

    // Phase 5: min-max norm + BCE partial sum (probs from registers)
    const bool donorm = (tmax > tmin);
    const float inv = donorm ? 1.0f / (tmax - tmin) : 0.0f;
    float lsum = 0.0f;
    #pragma unroll
    for (int k = 0; k < CH4; ++k) {
        float g  = garr[k];
        float rr = donorm ? (g - tmin) * inv : g;
        if (!anyA) rr = 0.0f;
        float s = pr[k];
        lsum += -(rr * __logf(s) + (1.0f - rr) * __logf(1.0f - s));
    }
    #pragma unroll
    for (int d = 16; d; d >>= 1)
        lsum += __shfl_xor_sync(0xffffffffu, lsum, d);
    if (lane == 0) fsm[wg] = lsum;
    __syncthreads();

    if (t == 0) {
        float tot = 0.0f;
        #pragma unroll
        for (int w = 0; w < 16; ++w) tot += fsm[w];
        g_partial[b] = tot;
        __threadfence();
        int old = atomicAdd(&g_count, 1);
        if (old == (int)gridDim.x - 1) {
            float s = 0.0f;
            const int nb = (int)gridDim.x;
            for (int i = 0; i < nb; ++i) s += g_partial[i];  // fixed order
            out[0] = s / ((float)nb * (float)TT);
            g_count = 0;     // reset for next graph replay
        }
    }
}

extern "C" void kernel_launch(void* const* d_in, const int* in_sizes, int n_in,
                              void* d_out, int out_size)
{
    const float* scores      = (const float*)d_in[0];
    // d_in[1] = labels (unused by the loss)
    const int*   point_label = (const int*)d_in[2];
    const int*   seqlen      = (const int*)d_in[3];
    const int*   step_p      = (const int*)d_in[4];
    float* out = (float*)d_out;

    const int B  = in_sizes[1];   // 64
    const int nb = B / 2;         // 32 abnormal videos

    glance_fused<<<nb, NT>>>(scores, point_label, seqlen, step_p, out);
}

// round 8
// speedup vs baseline: 5.7500x; 1.0238x over previous
#include <cuda_runtime.h>
#include <math.h>

// Fixed dataset shape: B=64, NCROPS=2, T=2048, nb=32
#define TT   2048
#define NT   512        // 16 warps: group0 = warps 0-7 (fwd), group1 = warps 8-15 (bwd)
#define GT   256        // threads per group
#define GCH  8          // elements per thread in group phases
#define CH4  4          // elements per thread in full-block phases
#define ALPHA_F 0.7f
#define MIN_MINING_STEP 50
#define SENT_LO (-(1 << 30))
#define BIGF 3.0e38f

__device__ float g_partial[64];
__device__ int   g_count = 0;

// group barrier (named): only the 256 threads of one group participate
__device__ __forceinline__ void gbar(int id) {
    asm volatile("bar.sync %0, %1;" :: "r"(id), "r"(GT) : "memory");
}

// ---- mining monoid: function (okIn,anchIn,hasIn) -> (okOut,anchOut,hasOut) ----
// fl bit0 = hasAnchor, bit1 = okPost (ok after last internal anchor)
struct MF { int fl; float aOut; float mPre; };

__device__ __forceinline__ MF mcomp(const MF L, const MF R) {
    MF C;
    const int lh = L.fl & 1, rh = R.fl & 1;
    C.aOut = rh ? R.aOut : L.aOut;
    C.mPre = lh ? L.mPre : fminf(L.mPre, R.mPre);
    int kp = rh ? (R.fl >> 1)
                : ((L.fl >> 1) & ((R.mPre >= ALPHA_F * L.aOut) ? 1 : 0));
    C.fl = (lh | rh) | ((kp & 1) << 1);
    return C;
}

// One mining direction: exact replay of the jax scan recurrence via
// serial-chunk + warp-shuffle scan + cross-warp compose (group-local).
// Operands (probs + anchor bitmask) are register-cached by the caller.
__device__ __forceinline__ void mine_dir(
    const float* sv, unsigned amask,
    unsigned char* __restrict__ smined,
    int* sfl, float* sa, float* sm,
    int lane, int wig, int wg, int barId, int rev, int L, int base)
{
    // pass 1: serial thread aggregate (compose 8 element functions)
    MF acc;
    #pragma unroll
    for (int k = 0; k < GCH; ++k) {
        float s = sv[k];
        int   a = (amask >> k) & 1;
        MF e; e.fl = a ? 3 : 2; e.aOut = a ? s : 0.0f; e.mPre = a ? BIGF : s;
        acc = (k == 0) ? e : mcomp(acc, e);
    }

    // warp inclusive scan
    MF inc = acc;
    #pragma unroll
    for (int d = 1; d < 32; d <<= 1) {
        MF v;
        v.fl   = __shfl_up_sync(0xffffffffu, inc.fl,   d);
        v.aOut = __shfl_up_sync(0xffffffffu, inc.aOut, d);
        v.mPre = __shfl_up_sync(0xffffffffu, inc.mPre, d);
        if (lane >= d) inc = mcomp(v, inc);
    }
    if (lane == 31) { sfl[wg] = inc.fl; sa[wg] = inc.aOut; sm[wg] = inc.mPre; }
    gbar(barId);

    // prefix over preceding warps of this group (serial composes)
    MF wp; int hasWp = 0;
    const int wbase = wg - wig;
    for (int w = wbase; w < wg; ++w) {
        MF v; v.fl = sfl[w]; v.aOut = sa[w]; v.mPre = sm[w];
        wp = hasWp ? mcomp(wp, v) : v;
        hasWp = 1;
    }
    // thread-exclusive within warp
    MF te;
    te.fl   = __shfl_up_sync(0xffffffffu, inc.fl,   1);
    te.aOut = __shfl_up_sync(0xffffffffu, inc.aOut, 1);
    te.mPre = __shfl_up_sync(0xffffffffu, inc.mPre, 1);
    const int hasTe = (lane > 0);
    MF P; int hasP = 0;
    if (hasWp && hasTe)      { P = mcomp(wp, te); hasP = 1; }
    else if (hasWp)          { P = wp;            hasP = 1; }
    else if (hasTe)          { P = te;            hasP = 1; }

    // apply prefix to canonical init (ok=true, anch=0, has=false)
    int   has  = hasP ? (P.fl & 1) : 0;
    int   ok   = has ? ((P.fl >> 1) & 1) : 1;
    float anch = has ? P.aOut : 0.0f;

    // pass 2: serial replay emitting grown flags (operands from registers)
    #pragma unroll
    for (int k = 0; k < GCH; ++k) {
        float s = sv[k];
        int   a = (amask >> k) & 1;
        int cond  = (s >= ALPHA_F * anch) ? 1 : 0;
        int grown = ok & cond & has;
        int idx = base + k;
        int pos = rev ? (TT - 1 - idx) : idx;
        if (grown && (rev || pos < L)) smined[pos] = 1;  // fwd masked by seqlen
        ok   = a ? 1 : grown;
        anch = a ? s : anch;
        has |= a;
    }
}

// Distance-to-previous-set (in idx coordinates) via group-local max scan
__device__ __forceinline__ void dist_dir(
    const unsigned char* __restrict__ smined, int* __restrict__ dout,
    int* iw, int gt, int lane, int wig, int wg, int barId, int rev)
{
    const int base = gt * GCH;
    int incl[GCH]; int run = SENT_LO;
    #pragma unroll
    for (int k = 0; k < GCH; ++k) {
        int idx = base + k;
        int pos = rev ? (TT - 1 - idx) : idx;
        if (smined[pos]) run = idx;
        incl[k] = run;
    }
    int v = run;
    #pragma unroll
    for (int d = 1; d < 32; d <<= 1) {
        int u = __shfl_up_sync(0xffffffffu, v, d);
        if (lane >= d) v = max(v, u);
    }
    if (lane == 31) iw[wg] = v;
    gbar(barId);
    int carry = SENT_LO;
    const int wbase = wg - wig;
    for (int w = wbase; w < wg; ++w) carry = max(carry, iw[w]);
    int te = __shfl_up_sync(0xffffffffu, v, 1);
    if (lane == 0) te = SENT_LO;
    carry = max(carry, te);
    #pragma unroll
    for (int k = 0; k < GCH; ++k) {
        int idx = base + k;
        int pos = rev ? (TT - 1 - idx) : idx;
        int pv = max(carry, incl[k]);
        dout[pos] = idx - pv;          // distance (huge when none)
    }
}

__global__ __launch_bounds__(NT, 1)
void glance_fused(const float* __restrict__ scores,
                  const int* __restrict__ point_label,
                  const int* __restrict__ seqlen,
                  const int* __restrict__ step_p,
                  float* __restrict__ out)
{
    const int b = blockIdx.x;
    const int t = threadIdx.x;

    __shared__ float sprob[TT];
    __shared__ int   sprevd[TT];
    __shared__ int   snextd[TT];
    __shared__ unsigned char sanch[TT];
    __shared__ unsigned char smined[TT];
    __shared__ int   sfl[16]; __shared__ float sa[16]; __shared__ float sm[16];
    __shared__ int   iw[16];
    __shared__ float rmn[16], rmx[16], rsv[16], rsgd[16], rsd[16];

    // early scalar loads (overlap with phase 1 DRAM latency)
    const int L   = seqlen[b];
    const int stp = step_p[0];

    // Phase 1: vectorized sigmoid + crop-mean; BCE logs precomputed here.
    //   ea=e^-a, ec=e^-c; num1=2+ea+ec; num2=2*ea*ec+ea+ec; den=num1+num2
    //   p = num1/den ; log(p)=log(num1*rcp) ; log(1-p)=log(num2*rcp)
    // -> 2 EX2 + 1 RCP + 2 LG2 per element (was 6 MUFU).
    const float4* r0 = (const float4*)(scores + (size_t)(2 * b) * TT);
    const float4* r1 = (const float4*)(scores + (size_t)(2 * b + 1) * TT);
    const int4*   pl = (const int4*)(point_label + (size_t)b * TT);
    const float4 avv = r0[t];
    const float4 cvv = r1[t];
    const int4   qvv = pl[t];
    const float aa[4] = {avv.x, avv.y, avv.z, avv.w};
    const float cc[4] = {cvv.x, cvv.y, cvv.z, cvv.w};
    const int   qq[4] = {qvv.x, qvv.y, qvv.z, qvv.w};
    const int base4 = t * CH4;
    float uu[CH4], vv[CH4];
    #pragma unroll
    for (int k = 0; k < CH4; ++k) {
        float ea = __expf(-aa[k]);
        float ec = __expf(-cc[k]);
        float n1 = 2.0f + ea + ec;
        float n2 = fmaf(2.0f * ea, ec, ea + ec);
        float rc = __frcp_rn(n1 + n2);
        float p  = n1 * rc;
        sprob[base4 + k] = p;
        uu[k] = __logf(n1 * rc);
        vv[k] = __logf(n2 * rc);
        int af = (qq[k] > 0) ? 1 : 0;
        sanch[base4 + k]  = (unsigned char)af;
        smined[base4 + k] = (unsigned char)af;
    }
    __syncthreads();

    const int lane = t & 31, wg = t >> 5, grp = t >> 8, wig = wg & 7;
    const int gt = t & (GT - 1), barId = 1 + grp;
    const int gbase = gt * GCH;

    // Phase 2: mining — fwd (group 0) and bwd (group 1) run CONCURRENTLY
    if (stp >= MIN_MINING_STEP) {
        float sv[GCH]; unsigned amask = 0;
        #pragma unroll
        for (int k = 0; k < GCH; ++k) {
            int idx = gbase + k;
            int pos = grp ? (TT - 1 - idx) : idx;
            sv[k] = sprob[pos];
            amask |= ((unsigned)sanch[pos]) << k;
        }
        mine_dir(sv, amask, smined, sfl, sa, sm,
                 lane, wig, wg, barId, grp, L, gbase);
    }
    __syncthreads();

    // Phase 3: distance transforms — prev (group 0) / next (group 1) concurrent
    if (grp == 0) dist_dir(smined, sprevd, iw, gt, lane, wig, wg, barId, 0);
    else          dist_dir(smined, snextd, iw, gt, lane, wig, wg, barId, 1);
    __syncthreads();

    // Phase 4: splat + FUSED BCE reduction.
    // g = exp(coef*d^2), d = nearest mined distance.
    // loss = -Sv - inv*(Sgd - tmin*Sd)   [donorm]
    //      = -Sv - Sgd                   [tmax==tmin; also covers no-anchor g==0]
    const float coef = -200.0f / ((float)(TT - 1) * (float)(TT - 1));
    float lmin = 1e30f, lmax = -1e30f, Sv = 0.0f, Sgd = 0.0f, Sd = 0.0f;
    #pragma unroll
    for (int k = 0; k < CH4; ++k) {
        int pos = base4 + k;
        int d = min(sprevd[pos], snextd[pos]);
        float fd = (float)d;
        float g = __expf(coef * fd * fd);
        lmin = fminf(lmin, g);
        lmax = fmaxf(lmax, g);
        float du = uu[k] - vv[k];
        Sv += vv[k];
        Sgd = fmaf(g, du, Sgd);
        Sd += du;
    }
    #pragma unroll
    for (int d = 16; d; d >>= 1) {
        lmin = fminf(lmin, __shfl_xor_sync(0xffffffffu, lmin, d));
        lmax = fmaxf(lmax, __shfl_xor_sync(0xffffffffu, lmax, d));
        Sv  += __shfl_xor_sync(0xffffffffu, Sv,  d);
        Sgd += __shfl_xor_sync(0xffffffffu, Sgd, d);
        Sd  += __shfl_xor_sync(0xffffffffu, Sd,  d);
    }
    if (lane == 0) {
        rmn[wg] = lmin; rmx[wg] = lmax;
        rsv[wg] = Sv;   rsgd[wg] = Sgd; rsd[wg] = Sd;
    }
    __syncthreads();

    if (t == 0) {
        float tmin = 1e30f, tmax = -1e30f, sv_ = 0.0f, sgd_ = 0.0f, sd_ = 0.0f;
        #pragma unroll
        for (int w = 0; w < 16; ++w) {
            tmin = fminf(tmin, rmn[w]);
            tmax = fmaxf(tmax, rmx[w]);
            sv_  += rsv[w];
            sgd_ += rsgd[w];
            sd_  += rsd[w];
        }
        float loss;
        if (tmax > tmin) {
            float inv = 1.0f / (tmax - tmin);
            loss = -sv_ - inv * (sgd_ - tmin * sd_);
        } else {
            loss = -sv_ - sgd_;
        }
        g_partial[b] = loss;
        __threadfence();
        int old = atomicAdd(&g_count, 1);
        if (old == (int)gridDim.x - 1) {
            float s = 0.0f;
            const int nb = (int)gridDim.x;
            for (int i = 0; i < nb; ++i) s += g_partial[i];  // fixed order
            out[0] = s / ((float)nb * (float)TT);
            g_count = 0;     // reset for next graph replay
        }
    }
}

extern "C" void kernel_launch(void* const* d_in, const int* in_sizes, int n_in,
                              void* d_out, int out_size)
{
    const float* scores      = (const float*)d_in[0];
    // d_in[1] = labels (unused by the loss)
    const int*   point_label = (const int*)d_in[2];
    const int*   seqlen      = (const int*)d_in[3];
    const int*   step_p      = (const int*)d_in[4];
    float* out = (float*)d_out;

    const int B  = in_sizes[1];   // 64
    const int nb = B / 2;         // 32 abnormal videos

    glance_fused<<<nb, NT>>>(scores, point_label, seqlen, step_p, out);
}